// round 1
// baseline (speedup 1.0000x reference)
#include <cuda_runtime.h>

#define N_NODES 20000
#define DEG     32
#define D_IN    128
#define D_OUT   256
#define E_EDGES (N_NODES * DEG)
#define BM      32      // nodes per block (20000 = 625 * 32 exactly)
#define KB      16      // K-tile for GEMM

__global__ __launch_bounds__(256, 3)
void sage_fused_kernel(const float* __restrict__ x,
                       const int*   __restrict__ col,     // edge_index row 1
                       const float* __restrict__ ew,
                       const float* __restrict__ Wl,
                       const float* __restrict__ bl,
                       const float* __restrict__ Wr,
                       float*       __restrict__ out)
{
    // A-tile: [BM][256]; cols 0..127 = x row, cols 128..255 = neigh row
    __shared__ float As[BM][D_OUT];
    __shared__ union {
        float Bs[KB][D_OUT];                       // 16 KB GEMM B-tile
        struct { int cols[BM * DEG]; float wts[BM * DEG]; } eb;  // 8 KB edge stage
    } u;

    const int tid   = threadIdx.x;
    const int node0 = blockIdx.x * BM;

    // ---- stage edges for this block's 32 nodes (row-contiguous layout) ----
    {
        const int ebase = node0 * DEG;
        #pragma unroll
        for (int i = 0; i < 4; i++) {
            int e = tid + i * 256;                 // 1024 edges
            u.eb.cols[e] = col[ebase + e];
            u.eb.wts[e]  = ew[ebase + e];
        }
    }

    // ---- load x rows into As[:, 0:128] (coalesced float4) ----
    {
        const int nl    = tid >> 3;                // 0..31 node-local
        const int chunk = tid & 7;                 // 16-float feature chunk
        const float4* xp = reinterpret_cast<const float4*>(
            x + (size_t)(node0 + nl) * D_IN + chunk * 16);
        float4* ap = reinterpret_cast<float4*>(&As[nl][chunk * 16]);
        #pragma unroll
        for (int j = 0; j < 4; j++) ap[j] = xp[j];
    }
    __syncthreads();

    // ---- aggregate: neigh = (sum w * x[col]) / sum w -> As[:, 128:256] ----
    {
        const int nl    = tid >> 3;
        const int chunk = tid & 7;
        float4 acc[4];
        #pragma unroll
        for (int j = 0; j < 4; j++) acc[j] = make_float4(0.f, 0.f, 0.f, 0.f);
        float deg = 0.f;

        #pragma unroll 4
        for (int e = 0; e < DEG; e++) {
            const int   c = u.eb.cols[nl * DEG + e];
            const float w = u.eb.wts[nl * DEG + e];
            deg += w;
            const float4* xp = reinterpret_cast<const float4*>(
                x + (size_t)c * D_IN + chunk * 16);
            #pragma unroll
            for (int j = 0; j < 4; j++) {
                float4 v = xp[j];
                acc[j].x += w * v.x; acc[j].y += w * v.y;
                acc[j].z += w * v.z; acc[j].w += w * v.w;
            }
        }
        if (deg == 0.f) deg = 1.f;
        const float inv = 1.f / deg;
        float4* ap = reinterpret_cast<float4*>(&As[nl][D_IN + chunk * 16]);
        #pragma unroll
        for (int j = 0; j < 4; j++)
            ap[j] = make_float4(acc[j].x * inv, acc[j].y * inv,
                                acc[j].z * inv, acc[j].w * inv);
    }
    __syncthreads();   // edges no longer needed; u can become Bs

    // ---- GEMM: out[BM,256] = As[BM,256] @ [Wl;Wr](256,256) + bl ----
    const int ty = tid >> 5;   // 0..7 -> rows ty*4 .. ty*4+3
    const int tx = tid & 31;   // cols tx*8 .. tx*8+7
    float acc[4][8];
    #pragma unroll
    for (int r = 0; r < 4; r++)
        #pragma unroll
        for (int c = 0; c < 8; c++) acc[r][c] = 0.f;

    for (int k0 = 0; k0 < D_OUT; k0 += KB) {
        // stage B tile: row kr of [Wl;Wr], 16 rows x 256 cols
        const int kr = tid >> 4;            // 0..15
        const int cc = (tid & 15) * 16;     // 16-float column chunk
        const int kg = k0 + kr;
        const float* bsrc = (kg < D_IN) ? (Wl + (size_t)kg * D_OUT + cc)
                                        : (Wr + (size_t)(kg - D_IN) * D_OUT + cc);
        float4*       bp = reinterpret_cast<float4*>(&u.Bs[kr][cc]);
        const float4* gp = reinterpret_cast<const float4*>(bsrc);
        #pragma unroll
        for (int j = 0; j < 4; j++) bp[j] = gp[j];
        __syncthreads();

        #pragma unroll
        for (int kk = 0; kk < KB; kk++) {
            float a[4];
            #pragma unroll
            for (int r = 0; r < 4; r++) a[r] = As[ty * 4 + r][k0 + kk];  // broadcast
            const float4* b4 = reinterpret_cast<const float4*>(&u.Bs[kk][tx * 8]);
            float4 b0 = b4[0], b1 = b4[1];
            float b[8] = {b0.x, b0.y, b0.z, b0.w, b1.x, b1.y, b1.z, b1.w};
            #pragma unroll
            for (int r = 0; r < 4; r++)
                #pragma unroll
                for (int c = 0; c < 8; c++) acc[r][c] += a[r] * b[c];
        }
        __syncthreads();
    }

    // ---- epilogue: + bias, store ----
    float4 blv0 = reinterpret_cast<const float4*>(bl + tx * 8)[0];
    float4 blv1 = reinterpret_cast<const float4*>(bl + tx * 8)[1];
    const float blv[8] = {blv0.x, blv0.y, blv0.z, blv0.w,
                          blv1.x, blv1.y, blv1.z, blv1.w};
    #pragma unroll
    for (int r = 0; r < 4; r++) {
        const int row = node0 + ty * 4 + r;
        float4* op = reinterpret_cast<float4*>(out + (size_t)row * D_OUT + tx * 8);
        op[0] = make_float4(acc[r][0] + blv[0], acc[r][1] + blv[1],
                            acc[r][2] + blv[2], acc[r][3] + blv[3]);
        op[1] = make_float4(acc[r][4] + blv[4], acc[r][5] + blv[5],
                            acc[r][6] + blv[6], acc[r][7] + blv[7]);
    }
}

extern "C" void kernel_launch(void* const* d_in, const int* in_sizes, int n_in,
                              void* d_out, int out_size)
{
    const float* x    = (const float*)d_in[0];
    const int*   ei   = (const int*)  d_in[1];   // [2, E]
    const float* ew   = (const float*)d_in[2];
    const float* Wl   = (const float*)d_in[3];
    const float* bl   = (const float*)d_in[4];
    const float* Wr   = (const float*)d_in[5];
    float*       out  = (float*)d_out;

    const int* col = ei + E_EDGES;   // second row of edge_index

    sage_fused_kernel<<<N_NODES / BM, 256>>>(x, col, ew, Wl, bl, Wr, out);
}

// round 2
// speedup vs baseline: 1.1542x; 1.1542x over previous
#include <cuda_runtime.h>

#define N_NODES 20000
#define DEG     32
#define D_IN    128
#define D_OUT   256
#define E_EDGES (N_NODES * DEG)
#define BM      32      // nodes per block (20000 = 625 * 32 exactly)
#define KB      16      // K-tile for GEMM

__global__ __launch_bounds__(256, 3)
void sage_fused_kernel(const float* __restrict__ x,
                       const int*   __restrict__ col,     // edge_index row 1
                       const float* __restrict__ ew,
                       const float* __restrict__ Wl,
                       const float* __restrict__ bl,
                       const float* __restrict__ Wr,
                       float*       __restrict__ out)
{
    // A-tile: [BM][256]; cols 0..127 = x row, cols 128..255 = neigh row
    __shared__ float As[BM][D_OUT];
    __shared__ union {
        float Bs[KB][D_OUT];                       // 16 KB GEMM B-tile
        struct { int cols[BM * DEG]; float wts[BM * DEG]; } eb;  // 8 KB edge stage
    } u;

    const int tid   = threadIdx.x;
    const int wi    = tid >> 5;     // warp 0..7
    const int lane  = tid & 31;
    const int node0 = blockIdx.x * BM;

    // ---- stage edges for this block's 32 nodes (row-contiguous layout) ----
    {
        const int ebase = node0 * DEG;
        #pragma unroll
        for (int i = 0; i < 4; i++) {
            int e = tid + i * 256;                 // 1024 edges
            u.eb.cols[e] = col[ebase + e];
            u.eb.wts[e]  = ew[ebase + e];
        }
    }

    // ---- load self x rows into As[:, 0:128]: warp wi -> rows wi*4..+3,
    //      32 lanes x float4 cover the whole 128-float row (dense LDG.128) ----
    #pragma unroll
    for (int r = 0; r < 4; r++) {
        const int nl = wi * 4 + r;
        float4 v = *reinterpret_cast<const float4*>(
            x + (size_t)(node0 + nl) * D_IN + lane * 4);
        *reinterpret_cast<float4*>(&As[nl][lane * 4]) = v;
    }
    __syncthreads();

    // ---- gather: warp-per-node, one dense row-read per edge ----
    #pragma unroll
    for (int r = 0; r < 4; r++) {
        const int nl = wi * 4 + r;
        float4 acc = make_float4(0.f, 0.f, 0.f, 0.f);
        float  deg = 0.f;
        #pragma unroll 4
        for (int e = 0; e < DEG; e++) {
            const int   c = u.eb.cols[nl * DEG + e];   // broadcast
            const float w = u.eb.wts[nl * DEG + e];    // broadcast
            deg += w;
            float4 v = *reinterpret_cast<const float4*>(
                x + (size_t)c * D_IN + lane * 4);      // 512B dense per warp
            acc.x += w * v.x; acc.y += w * v.y;
            acc.z += w * v.z; acc.w += w * v.w;
        }
        if (deg == 0.f) deg = 1.f;
        const float inv = 1.f / deg;
        *reinterpret_cast<float4*>(&As[nl][D_IN + lane * 4]) =
            make_float4(acc.x * inv, acc.y * inv, acc.z * inv, acc.w * inv);
    }
    __syncthreads();   // edges no longer needed; u can become Bs

    // ---- GEMM: out[BM,256] = As[BM,256] @ [Wl;Wr](256,256) + bl ----
    const int ty = wi;         // rows ty*4 .. ty*4+3
    const int tx = lane;       // cols tx*8 .. tx*8+7
    float acc[4][8];
    #pragma unroll
    for (int r = 0; r < 4; r++)
        #pragma unroll
        for (int c = 0; c < 8; c++) acc[r][c] = 0.f;

    for (int k0 = 0; k0 < D_OUT; k0 += KB) {
        // stage B tile: row kr of [Wl;Wr], 16 rows x 256 cols
        const int kr = tid >> 4;            // 0..15
        const int cc = (tid & 15) * 16;     // 16-float column chunk
        const int kg = k0 + kr;
        const float* bsrc = (kg < D_IN) ? (Wl + (size_t)kg * D_OUT + cc)
                                        : (Wr + (size_t)(kg - D_IN) * D_OUT + cc);
        float4*       bp = reinterpret_cast<float4*>(&u.Bs[kr][cc]);
        const float4* gp = reinterpret_cast<const float4*>(bsrc);
        #pragma unroll
        for (int j = 0; j < 4; j++) bp[j] = gp[j];
        __syncthreads();

        #pragma unroll
        for (int kk = 0; kk < KB; kk++) {
            float a[4];
            #pragma unroll
            for (int r = 0; r < 4; r++) a[r] = As[ty * 4 + r][k0 + kk];  // broadcast
            const float4* b4 = reinterpret_cast<const float4*>(&u.Bs[kk][tx * 8]);
            float4 b0 = b4[0], b1 = b4[1];
            float b[8] = {b0.x, b0.y, b0.z, b0.w, b1.x, b1.y, b1.z, b1.w};
            #pragma unroll
            for (int r = 0; r < 4; r++)
                #pragma unroll
                for (int c = 0; c < 8; c++) acc[r][c] += a[r] * b[c];
        }
        __syncthreads();
    }

    // ---- epilogue: + bias, store ----
    float4 blv0 = reinterpret_cast<const float4*>(bl + tx * 8)[0];
    float4 blv1 = reinterpret_cast<const float4*>(bl + tx * 8)[1];
    const float blv[8] = {blv0.x, blv0.y, blv0.z, blv0.w,
                          blv1.x, blv1.y, blv1.z, blv1.w};
    #pragma unroll
    for (int r = 0; r < 4; r++) {
        const int row = node0 + ty * 4 + r;
        float4* op = reinterpret_cast<float4*>(out + (size_t)row * D_OUT + tx * 8);
        op[0] = make_float4(acc[r][0] + blv[0], acc[r][1] + blv[1],
                            acc[r][2] + blv[2], acc[r][3] + blv[3]);
        op[1] = make_float4(acc[r][4] + blv[4], acc[r][5] + blv[5],
                            acc[r][6] + blv[6], acc[r][7] + blv[7]);
    }
}

extern "C" void kernel_launch(void* const* d_in, const int* in_sizes, int n_in,
                              void* d_out, int out_size)
{
    const float* x    = (const float*)d_in[0];
    const int*   ei   = (const int*)  d_in[1];   // [2, E]
    const float* ew   = (const float*)d_in[2];
    const float* Wl   = (const float*)d_in[3];
    const float* bl   = (const float*)d_in[4];
    const float* Wr   = (const float*)d_in[5];
    float*       out  = (float*)d_out;

    const int* col = ei + E_EDGES;   // second row of edge_index

    sage_fused_kernel<<<N_NODES / BM, 256>>>(x, col, ew, Wl, bl, Wr, out);
}

// round 3
// speedup vs baseline: 1.1813x; 1.0235x over previous
#include <cuda_runtime.h>

#define N_NODES 20000
#define DEG     32
#define D_IN    128
#define D_OUT   256
#define E_EDGES (N_NODES * DEG)
#define BM      32      // nodes per block (20000 = 625 * 32 exactly)
#define KB      16      // K-tile for GEMM

typedef unsigned long long u64;

__device__ __forceinline__ u64 dup2(float a) {
    u64 r; asm("mov.b64 %0, {%1, %1};" : "=l"(r) : "f"(a)); return r;
}
__device__ __forceinline__ void fma2(u64& d, u64 a, u64 b) {
    asm("fma.rn.f32x2 %0, %1, %2, %0;" : "+l"(d) : "l"(a), "l"(b));
}
__device__ __forceinline__ u64 mul2(u64 a, u64 b) {
    u64 r; asm("mul.rn.f32x2 %0, %1, %2;" : "=l"(r) : "l"(a), "l"(b)); return r;
}
__device__ __forceinline__ u64 add2(u64 a, u64 b) {
    u64 r; asm("add.rn.f32x2 %0, %1, %2;" : "=l"(r) : "l"(a), "l"(b)); return r;
}

__global__ __launch_bounds__(256, 3)
void sage_fused_kernel(const float* __restrict__ x,
                       const int*   __restrict__ col,     // edge_index row 1
                       const float* __restrict__ ew,
                       const float* __restrict__ Wl,
                       const float* __restrict__ bl,
                       const float* __restrict__ Wr,
                       float*       __restrict__ out)
{
    // A-tile: [BM][256]; cols 0..127 = x row, cols 128..255 = neigh row
    __shared__ float As[BM][D_OUT];
    __shared__ union {
        float Bs[KB][D_OUT];          // 16 KB GEMM B-tile
        int2  eb[BM * DEG];           // 8 KB edge stage: {col, w_bits}
    } u;

    const int tid   = threadIdx.x;
    const int wi    = tid >> 5;     // warp 0..7
    const int lane  = tid & 31;
    const int node0 = blockIdx.x * BM;

    // ---- stage edges interleaved: one LDS.64 per edge later ----
    {
        const int ebase = node0 * DEG;
        #pragma unroll
        for (int i = 0; i < 4; i++) {
            int e = tid + i * 256;                 // 1024 edges
            u.eb[e] = make_int2(col[ebase + e], __float_as_int(ew[ebase + e]));
        }
    }

    // ---- load self x rows into As[:, 0:128]: warp-wide dense 512B reads ----
    #pragma unroll
    for (int r = 0; r < 4; r++) {
        const int nl = wi * 4 + r;
        float4 v = *reinterpret_cast<const float4*>(
            x + (size_t)(node0 + nl) * D_IN + lane * 4);
        *reinterpret_cast<float4*>(&As[nl][lane * 4]) = v;
    }
    __syncthreads();

    // ---- gather: warp-per-node, dense row reads, packed f32x2 math ----
    #pragma unroll
    for (int r = 0; r < 4; r++) {
        const int nl = wi * 4 + r;
        u64 acc0 = 0ull, acc1 = 0ull;   // (0.f,0.f) pairs
        float deg = 0.f;
        #pragma unroll 8
        for (int e = 0; e < DEG; e++) {
            const int2 cw = u.eb[nl * DEG + e];            // broadcast LDS.64
            const float w = __int_as_float(cw.y);
            deg += w;
            ulonglong2 v = *reinterpret_cast<const ulonglong2*>(
                x + (size_t)cw.x * D_IN + lane * 4);       // 512B dense / warp
            const u64 wd = dup2(w);
            fma2(acc0, wd, v.x);
            fma2(acc1, wd, v.y);
        }
        if (deg == 0.f) deg = 1.f;
        const u64 iv = dup2(1.f / deg);
        ulonglong2 res;
        res.x = mul2(acc0, iv);
        res.y = mul2(acc1, iv);
        *reinterpret_cast<ulonglong2*>(&As[nl][D_IN + lane * 4]) = res;
    }
    __syncthreads();   // edges no longer needed; u becomes Bs

    // ---- GEMM: out[BM,256] = As[BM,256] @ [Wl;Wr](256,256) + bl ----
    const int ty = wi;         // rows ty*4 .. ty*4+3
    const int tx = lane;       // cols tx*8 .. tx*8+7 (4 packed pairs)
    u64 acc2[4][4];
    #pragma unroll
    for (int r = 0; r < 4; r++)
        #pragma unroll
        for (int c = 0; c < 4; c++) acc2[r][c] = 0ull;

    for (int k0 = 0; k0 < D_OUT; k0 += KB) {
        // stage B tile: 16 rows x 256 cols of [Wl;Wr]
        const int kr = tid >> 4;            // 0..15
        const int cc = (tid & 15) * 16;     // 16-float column chunk
        const int kg = k0 + kr;
        const float* bsrc = (kg < D_IN) ? (Wl + (size_t)kg * D_OUT + cc)
                                        : (Wr + (size_t)(kg - D_IN) * D_OUT + cc);
        float4*       bp = reinterpret_cast<float4*>(&u.Bs[kr][cc]);
        const float4* gp = reinterpret_cast<const float4*>(bsrc);
        #pragma unroll
        for (int j = 0; j < 4; j++) bp[j] = gp[j];
        __syncthreads();

        #pragma unroll
        for (int kk = 0; kk < KB; kk++) {
            u64 a2[4];
            #pragma unroll
            for (int r = 0; r < 4; r++)
                a2[r] = dup2(As[ty * 4 + r][k0 + kk]);     // broadcast + dup
            ulonglong2 b01 = *reinterpret_cast<const ulonglong2*>(&u.Bs[kk][tx * 8]);
            ulonglong2 b23 = *reinterpret_cast<const ulonglong2*>(&u.Bs[kk][tx * 8 + 4]);
            u64 b[4] = {b01.x, b01.y, b23.x, b23.y};
            #pragma unroll
            for (int r = 0; r < 4; r++)
                #pragma unroll
                for (int c = 0; c < 4; c++)
                    fma2(acc2[r][c], a2[r], b[c]);         // FFMA2: 2 MACs/op
        }
        __syncthreads();
    }

    // ---- epilogue: + bias (packed), store 16B ----
    ulonglong2 bl01 = *reinterpret_cast<const ulonglong2*>(bl + tx * 8);
    ulonglong2 bl23 = *reinterpret_cast<const ulonglong2*>(bl + tx * 8 + 4);
    const u64 blv[4] = {bl01.x, bl01.y, bl23.x, bl23.y};
    #pragma unroll
    for (int r = 0; r < 4; r++) {
        const int row = node0 + ty * 4 + r;
        ulonglong2* op = reinterpret_cast<ulonglong2*>(out + (size_t)row * D_OUT + tx * 8);
        ulonglong2 o0, o1;
        o0.x = add2(acc2[r][0], blv[0]);
        o0.y = add2(acc2[r][1], blv[1]);
        o1.x = add2(acc2[r][2], blv[2]);
        o1.y = add2(acc2[r][3], blv[3]);
        op[0] = o0;
        op[1] = o1;
    }
}

extern "C" void kernel_launch(void* const* d_in, const int* in_sizes, int n_in,
                              void* d_out, int out_size)
{
    const float* x    = (const float*)d_in[0];
    const int*   ei   = (const int*)  d_in[1];   // [2, E]
    const float* ew   = (const float*)d_in[2];
    const float* Wl   = (const float*)d_in[3];
    const float* bl   = (const float*)d_in[4];
    const float* Wr   = (const float*)d_in[5];
    float*       out  = (float*)d_out;

    const int* col = ei + E_EDGES;   // second row of edge_index

    sage_fused_kernel<<<N_NODES / BM, 256>>>(x, col, ew, Wl, bl, Wr, out);
}

// round 4
// speedup vs baseline: 1.3915x; 1.1780x over previous
#include <cuda_runtime.h>

#define N_NODES 20000
#define DEG     32
#define D_IN    128
#define D_OUT   256
#define E_EDGES (N_NODES * DEG)

// scratch for aggregated neighbor features (allowed: __device__ global)
__device__ float g_neigh[(size_t)N_NODES * D_IN];

typedef unsigned long long u64;

__device__ __forceinline__ u64 dup2(float a) {
    u64 r; asm("mov.b64 %0, {%1, %1};" : "=l"(r) : "f"(a)); return r;
}
__device__ __forceinline__ void fma2(u64& d, u64 a, u64 b) {
    asm("fma.rn.f32x2 %0, %1, %2, %0;" : "+l"(d) : "l"(a), "l"(b));
}
__device__ __forceinline__ u64 mul2(u64 a, u64 b) {
    u64 r; asm("mul.rn.f32x2 %0, %1, %2;" : "=l"(r) : "l"(a), "l"(b)); return r;
}
__device__ __forceinline__ void unpack2(float& lo, float& hi, u64 v) {
    asm("mov.b64 {%0, %1}, %2;" : "=f"(lo), "=f"(hi) : "l"(v));
}

// ---------------- Kernel 1: weighted-mean gather (warp per node) -------------
__global__ __launch_bounds__(256)
void gather_kernel(const float* __restrict__ x,
                   const int*   __restrict__ col,
                   const float* __restrict__ ew)
{
    __shared__ int2 eb[256];
    const int tid  = threadIdx.x;
    const int wi   = tid >> 5;
    const int lane = tid & 31;
    const int nodeBase = blockIdx.x * 8;        // 8 nodes per block
    const int ebase    = nodeBase * DEG;        // 256 edges, row-contiguous

    eb[tid] = make_int2(col[ebase + tid], __float_as_int(ew[ebase + tid]));
    __syncthreads();

    const int node = nodeBase + wi;
    u64 acc0 = 0ull, acc1 = 0ull;
    float deg = 0.f;
    #pragma unroll 8
    for (int e = 0; e < DEG; e++) {
        const int2 cw = eb[wi * DEG + e];              // broadcast LDS.64
        const float w = __int_as_float(cw.y);
        deg += w;
        ulonglong2 v = *reinterpret_cast<const ulonglong2*>(
            x + (size_t)cw.x * D_IN + lane * 4);       // dense 512B per warp
        const u64 wd = dup2(w);
        fma2(acc0, wd, v.x);
        fma2(acc1, wd, v.y);
    }
    if (deg == 0.f) deg = 1.f;
    const u64 iv = dup2(1.f / deg);
    ulonglong2 res;
    res.x = mul2(acc0, iv);
    res.y = mul2(acc1, iv);
    *reinterpret_cast<ulonglong2*>(g_neigh + (size_t)node * D_IN + lane * 4) = res;
}

// ---------------- Kernel 2: register-blocked GEMM ---------------------------
// out[M=20000, 256] = [x | neigh] (K=256) @ [Wl; Wr] + bl
#define TM 64
#define TN 128
#define TK 16
#define TM_PAD 68   // As row pad to reduce store bank conflicts

__global__ __launch_bounds__(256, 2)
void gemm_kernel(const float* __restrict__ x,
                 const float* __restrict__ Wl,
                 const float* __restrict__ bl,
                 const float* __restrict__ Wr,
                 float*       __restrict__ out)
{
    __shared__ float As[TK][TM_PAD];   // A^T tile: [k][m]
    __shared__ float Bs[TK][TN];       // B tile:   [k][n]
    const float* neigh = g_neigh;

    const int tid = threadIdx.x;
    const int ty  = tid >> 4;          // 0..15 -> rows ty*4..+3
    const int tx  = tid & 15;          // cols tx*8..+7
    const int node0 = blockIdx.x * TM;
    const int n0    = blockIdx.y * TN;

    // A loader: 16x64 tile, thread -> (row ar, k-chunk ak of 4)
    const int ar = tid >> 2;                    // 0..63
    const int ak = (tid & 3) * 4;               // 0,4,8,12
    int arow = node0 + ar; if (arow > N_NODES - 1) arow = N_NODES - 1;
    // B loader: 16x128 tile, thread -> (row kr, col-chunk nch of 8)
    const int kr  = tid >> 4;                   // 0..15
    const int nch = (tid & 15) * 8;

    float4 pa;           // A prefetch (4 floats)
    float4 pb0, pb1;     // B prefetch (8 floats)

    auto loadA = [&](int t) {
        const int k0 = t * TK;
        const float* src = (k0 < D_IN)
            ? (x     + (size_t)arow * D_IN + k0 + ak)
            : (neigh + (size_t)arow * D_IN + (k0 - D_IN) + ak);
        pa = *reinterpret_cast<const float4*>(src);
    };
    auto loadB = [&](int t) {
        const int kg = t * TK + kr;
        const float* src = (kg < D_IN)
            ? (Wl + (size_t)kg * D_OUT + n0 + nch)
            : (Wr + (size_t)(kg - D_IN) * D_OUT + n0 + nch);
        pb0 = reinterpret_cast<const float4*>(src)[0];
        pb1 = reinterpret_cast<const float4*>(src)[1];
    };

    u64 acc[2][8];       // 2 m-pairs (rows ty*4..+3) x 8 n-cols
    #pragma unroll
    for (int p = 0; p < 2; p++)
        #pragma unroll
        for (int n = 0; n < 8; n++) acc[p][n] = 0ull;

    loadA(0); loadB(0);

    #pragma unroll 1
    for (int t = 0; t < D_OUT / TK; t++) {
        __syncthreads();
        As[ak + 0][ar] = pa.x;
        As[ak + 1][ar] = pa.y;
        As[ak + 2][ar] = pa.z;
        As[ak + 3][ar] = pa.w;
        *reinterpret_cast<float4*>(&Bs[kr][nch])     = pb0;
        *reinterpret_cast<float4*>(&Bs[kr][nch + 4]) = pb1;
        __syncthreads();
        if (t < D_OUT / TK - 1) { loadA(t + 1); loadB(t + 1); }

        #pragma unroll
        for (int kk = 0; kk < TK; kk++) {
            // A m-pairs straight from LDS.128 (rows ty*4 .. ty*4+3)
            ulonglong2 av = *reinterpret_cast<const ulonglong2*>(&As[kk][ty * 4]);
            const u64 ap[2] = {av.x, av.y};
            float bv[8];
            *reinterpret_cast<float4*>(&bv[0]) =
                *reinterpret_cast<const float4*>(&Bs[kk][tx * 8]);
            *reinterpret_cast<float4*>(&bv[4]) =
                *reinterpret_cast<const float4*>(&Bs[kk][tx * 8 + 4]);
            #pragma unroll
            for (int n = 0; n < 8; n++) {
                const u64 bd = dup2(bv[n]);
                fma2(acc[0][n], ap[0], bd);
                fma2(acc[1][n], ap[1], bd);
            }
        }
    }

    // epilogue: unpack pairs, add bias, store
    float bb[8];
    *reinterpret_cast<float4*>(&bb[0]) =
        *reinterpret_cast<const float4*>(bl + n0 + tx * 8);
    *reinterpret_cast<float4*>(&bb[4]) =
        *reinterpret_cast<const float4*>(bl + n0 + tx * 8 + 4);

    #pragma unroll
    for (int p = 0; p < 2; p++) {
        float o0[8], o1[8];
        #pragma unroll
        for (int n = 0; n < 8; n++) {
            unpack2(o0[n], o1[n], acc[p][n]);
            o0[n] += bb[n];
            o1[n] += bb[n];
        }
        const int r0 = node0 + ty * 4 + 2 * p;
        if (r0 < N_NODES) {
            float* op = out + (size_t)r0 * D_OUT + n0 + tx * 8;
            reinterpret_cast<float4*>(op)[0] = make_float4(o0[0], o0[1], o0[2], o0[3]);
            reinterpret_cast<float4*>(op)[1] = make_float4(o0[4], o0[5], o0[6], o0[7]);
        }
        if (r0 + 1 < N_NODES) {
            float* op = out + (size_t)(r0 + 1) * D_OUT + n0 + tx * 8;
            reinterpret_cast<float4*>(op)[0] = make_float4(o1[0], o1[1], o1[2], o1[3]);
            reinterpret_cast<float4*>(op)[1] = make_float4(o1[4], o1[5], o1[6], o1[7]);
        }
    }
}

extern "C" void kernel_launch(void* const* d_in, const int* in_sizes, int n_in,
                              void* d_out, int out_size)
{
    const float* x  = (const float*)d_in[0];
    const int*   ei = (const int*)  d_in[1];   // [2, E]
    const float* ew = (const float*)d_in[2];
    const float* Wl = (const float*)d_in[3];
    const float* bl = (const float*)d_in[4];
    const float* Wr = (const float*)d_in[5];
    float*       out = (float*)d_out;

    const int* col = ei + E_EDGES;             // second row of edge_index

    gather_kernel<<<N_NODES / 8, 256>>>(x, col, ew);

    dim3 g2((N_NODES + TM - 1) / TM, D_OUT / TN);   // (313, 2)
    gemm_kernel<<<g2, 256>>>(x, Wl, bl, Wr, out);
}

// round 5
// speedup vs baseline: 1.6227x; 1.1661x over previous
#include <cuda_runtime.h>

#define N_NODES 20000
#define DEG     32
#define D_IN    128
#define D_OUT   256
#define E_EDGES (N_NODES * DEG)

// scratch for aggregated neighbor features (allowed: __device__ global)
__device__ float g_neigh[(size_t)N_NODES * D_IN];

typedef unsigned long long u64;

__device__ __forceinline__ u64 dup2(float a) {
    u64 r; asm("mov.b64 %0, {%1, %1};" : "=l"(r) : "f"(a)); return r;
}
__device__ __forceinline__ void fma2(u64& d, u64 a, u64 b) {
    asm("fma.rn.f32x2 %0, %1, %2, %0;" : "+l"(d) : "l"(a), "l"(b));
}
__device__ __forceinline__ u64 mul2(u64 a, u64 b) {
    u64 r; asm("mul.rn.f32x2 %0, %1, %2;" : "=l"(r) : "l"(a), "l"(b)); return r;
}
__device__ __forceinline__ void unpack2(float& lo, float& hi, u64 v) {
    asm("mov.b64 {%0, %1}, %2;" : "=f"(lo), "=f"(hi) : "l"(v));
}

// ---------------- Kernel 1: weighted-mean gather (warp per node) -------------
__global__ __launch_bounds__(256)
void gather_kernel(const float* __restrict__ x,
                   const int*   __restrict__ col,
                   const float* __restrict__ ew)
{
    __shared__ int2 eb[256];
    const int tid  = threadIdx.x;
    const int wi   = tid >> 5;
    const int lane = tid & 31;
    const int nodeBase = blockIdx.x * 8;        // 8 nodes per block
    const int ebase    = nodeBase * DEG;        // 256 edges, row-contiguous

    eb[tid] = make_int2(col[ebase + tid], __float_as_int(ew[ebase + tid]));
    __syncthreads();

    const int node = nodeBase + wi;
    u64 acc0 = 0ull, acc1 = 0ull;
    float deg = 0.f;
    #pragma unroll 8
    for (int e = 0; e < DEG; e++) {
        const int2 cw = eb[wi * DEG + e];              // broadcast LDS.64
        const float w = __int_as_float(cw.y);
        deg += w;
        ulonglong2 v = *reinterpret_cast<const ulonglong2*>(
            x + (size_t)cw.x * D_IN + lane * 4);       // dense 512B per warp
        const u64 wd = dup2(w);
        fma2(acc0, wd, v.x);
        fma2(acc1, wd, v.y);
    }
    if (deg == 0.f) deg = 1.f;
    const u64 iv = dup2(1.f / deg);
    ulonglong2 res;
    res.x = mul2(acc0, iv);
    res.y = mul2(acc1, iv);
    *reinterpret_cast<ulonglong2*>(g_neigh + (size_t)node * D_IN + lane * 4) = res;
}

// ---------------- Kernel 2: 128x128 register-blocked GEMM -------------------
// out[M=20000, 256] = [x | neigh] (K=256) @ [Wl; Wr] + bl
#define TM 128
#define TN 128
#define TK 16
#define NKT (D_OUT / TK)     // 16 k-tiles

__global__ __launch_bounds__(256, 1)
void gemm_kernel(const float* __restrict__ x,
                 const float* __restrict__ Wl,
                 const float* __restrict__ bl,
                 const float* __restrict__ Wr,
                 float*       __restrict__ out)
{
    __shared__ float As[TK][TM];       // A^T tile: [k][m]   8 KB
    __shared__ float Bs[TK][TN];       // B tile:   [k][n]   8 KB
    const float* neigh = g_neigh;

    const int tid = threadIdx.x;
    const int ty  = tid >> 4;          // 0..15 -> rows ty*8..+7
    const int tx  = tid & 15;          // cols tx*8..+7
    const int node0 = blockIdx.x * TM;
    const int n0    = blockIdx.y * TN;

    // A loader: 128 rows x 16 k; thread -> (row ar, k-chunk ak of 8)
    const int ar = tid >> 1;                    // 0..127
    const int ak = (tid & 1) * 8;               // 0 or 8
    int arow = node0 + ar; if (arow > N_NODES - 1) arow = N_NODES - 1;
    // B loader: 16 k x 128 n; thread -> (row kr, col-chunk nch of 8)
    const int kr  = tid >> 4;                   // 0..15
    const int nch = (tid & 15) * 8;

    float4 pa0, pa1;     // A prefetch (8 floats)
    float4 pb0, pb1;     // B prefetch (8 floats)

    auto loadA = [&](int t) {
        const int k0 = t * TK + ak;
        const float* src = (k0 < D_IN)
            ? (x     + (size_t)arow * D_IN + k0)
            : (neigh + (size_t)arow * D_IN + (k0 - D_IN));
        pa0 = reinterpret_cast<const float4*>(src)[0];
        pa1 = reinterpret_cast<const float4*>(src)[1];
    };
    auto loadB = [&](int t) {
        const int kg = t * TK + kr;
        const float* src = (kg < D_IN)
            ? (Wl + (size_t)kg * D_OUT + n0 + nch)
            : (Wr + (size_t)(kg - D_IN) * D_OUT + n0 + nch);
        pb0 = reinterpret_cast<const float4*>(src)[0];
        pb1 = reinterpret_cast<const float4*>(src)[1];
    };

    u64 acc[4][8];       // 4 m-pairs (rows ty*8..+7) x 8 n-cols
    #pragma unroll
    for (int p = 0; p < 4; p++)
        #pragma unroll
        for (int n = 0; n < 8; n++) acc[p][n] = 0ull;

    loadA(0); loadB(0);

    #pragma unroll 1
    for (int t = 0; t < NKT; t++) {
        __syncthreads();
        As[ak + 0][ar] = pa0.x;
        As[ak + 1][ar] = pa0.y;
        As[ak + 2][ar] = pa0.z;
        As[ak + 3][ar] = pa0.w;
        As[ak + 4][ar] = pa1.x;
        As[ak + 5][ar] = pa1.y;
        As[ak + 6][ar] = pa1.z;
        As[ak + 7][ar] = pa1.w;
        *reinterpret_cast<float4*>(&Bs[kr][nch])     = pb0;
        *reinterpret_cast<float4*>(&Bs[kr][nch + 4]) = pb1;
        __syncthreads();
        if (t < NKT - 1) { loadA(t + 1); loadB(t + 1); }

        #pragma unroll
        for (int kk = 0; kk < TK; kk++) {
            // 4 A m-pairs straight from 2x LDS.128 (rows ty*8 .. ty*8+7)
            ulonglong2 av0 = *reinterpret_cast<const ulonglong2*>(&As[kk][ty * 8]);
            ulonglong2 av1 = *reinterpret_cast<const ulonglong2*>(&As[kk][ty * 8 + 4]);
            const u64 ap[4] = {av0.x, av0.y, av1.x, av1.y};
            float bv[8];
            *reinterpret_cast<float4*>(&bv[0]) =
                *reinterpret_cast<const float4*>(&Bs[kk][tx * 8]);
            *reinterpret_cast<float4*>(&bv[4]) =
                *reinterpret_cast<const float4*>(&Bs[kk][tx * 8 + 4]);
            #pragma unroll
            for (int n = 0; n < 8; n++) {
                const u64 bd = dup2(bv[n]);
                #pragma unroll
                for (int p = 0; p < 4; p++)
                    fma2(acc[p][n], ap[p], bd);        // FFMA2: 2 MACs/op
            }
        }
    }

    // epilogue: unpack pairs, add bias, predicated stores
    float bb[8];
    *reinterpret_cast<float4*>(&bb[0]) =
        *reinterpret_cast<const float4*>(bl + n0 + tx * 8);
    *reinterpret_cast<float4*>(&bb[4]) =
        *reinterpret_cast<const float4*>(bl + n0 + tx * 8 + 4);

    #pragma unroll
    for (int p = 0; p < 4; p++) {
        float o0[8], o1[8];
        #pragma unroll
        for (int n = 0; n < 8; n++) {
            unpack2(o0[n], o1[n], acc[p][n]);
            o0[n] += bb[n];
            o1[n] += bb[n];
        }
        const int r0 = node0 + ty * 8 + 2 * p;
        if (r0 < N_NODES) {
            float* op = out + (size_t)r0 * D_OUT + n0 + tx * 8;
            reinterpret_cast<float4*>(op)[0] = make_float4(o0[0], o0[1], o0[2], o0[3]);
            reinterpret_cast<float4*>(op)[1] = make_float4(o0[4], o0[5], o0[6], o0[7]);
        }
        if (r0 + 1 < N_NODES) {
            float* op = out + (size_t)(r0 + 1) * D_OUT + n0 + tx * 8;
            reinterpret_cast<float4*>(op)[0] = make_float4(o1[0], o1[1], o1[2], o1[3]);
            reinterpret_cast<float4*>(op)[1] = make_float4(o1[4], o1[5], o1[6], o1[7]);
        }
    }
}

extern "C" void kernel_launch(void* const* d_in, const int* in_sizes, int n_in,
                              void* d_out, int out_size)
{
    const float* x  = (const float*)d_in[0];
    const int*   ei = (const int*)  d_in[1];   // [2, E]
    const float* ew = (const float*)d_in[2];
    const float* Wl = (const float*)d_in[3];
    const float* bl = (const float*)d_in[4];
    const float* Wr = (const float*)d_in[5];
    float*       out = (float*)d_out;

    const int* col = ei + E_EDGES;             // second row of edge_index

    gather_kernel<<<N_NODES / 8, 256>>>(x, col, ew);

    dim3 g2((N_NODES + TM - 1) / TM, D_OUT / TN);   // (157, 2)
    gemm_kernel<<<g2, 256>>>(x, Wl, bl, Wr, out);
}

// round 8
// speedup vs baseline: 2.8809x; 1.7754x over previous
#include <cuda_runtime.h>
#include <cuda_bf16.h>
#include <cstdint>
#include <cstddef>

#define N_NODES 20000
#define DEG     32
#define D_IN    128
#define D_OUT   256
#define E_EDGES (N_NODES * DEG)
#define MTILES  1250             // 20000 / 16 exactly

// A images in mma.sync fragment-major layout:
//   uint4 index = (mtile*16 + ktile)*32 + lane ; holds {a0,a1,a2,a3}
__device__ __nv_bfloat16 g_Ah[(size_t)N_NODES * D_OUT];
__device__ __nv_bfloat16 g_Al[(size_t)N_NODES * D_OUT];
// B images (256x256), fragment-major:
//   uint4 index = (ktile*16 + G*4 + p)*32 + lane ; comps = {t(2p).b0,t(2p).b1,t(2p+1).b0,t(2p+1).b1}
__device__ __nv_bfloat16 g_Bh[D_OUT * D_OUT];
__device__ __nv_bfloat16 g_Bl[D_OUT * D_OUT];

typedef unsigned long long u64;

__device__ __forceinline__ u64 dup2(float a) {
    u64 r; asm("mov.b64 %0, {%1, %1};" : "=l"(r) : "f"(a)); return r;
}
__device__ __forceinline__ void fma2(u64& d, u64 a, u64 b) {
    asm("fma.rn.f32x2 %0, %1, %2, %0;" : "+l"(d) : "l"(a), "l"(b));
}
__device__ __forceinline__ u64 mul2(u64 a, u64 b) {
    u64 r; asm("mul.rn.f32x2 %0, %1, %2;" : "=l"(r) : "l"(a), "l"(b)); return r;
}
__device__ __forceinline__ void unpack2(float& lo, float& hi, u64 v) {
    asm("mov.b64 {%0, %1}, %2;" : "=f"(lo), "=f"(hi) : "l"(v));
}
__device__ __forceinline__ uint32_t pkbf(__nv_bfloat16 a, __nv_bfloat16 b) {
    return (uint32_t)__bfloat16_as_ushort(a)
         | ((uint32_t)__bfloat16_as_ushort(b) << 16);
}
__device__ __forceinline__ void split_bf(float v, __nv_bfloat16& h, __nv_bfloat16& l) {
    h = __float2bfloat16(v);
    l = __float2bfloat16(v - __bfloat162float(h));
}

// ------------- Kernel 1: gather + frag-layout A images (block = 1 mtile) ----
#define SROW 260   // padded row stride (floats); 260*4 % 16 == 0 -> float4 ok

__global__ __launch_bounds__(256)
void gather_kernel(const float* __restrict__ x,
                   const int*   __restrict__ col,
                   const float* __restrict__ ew)
{
    __shared__ int2  eb[512];
    __shared__ float rows[16][SROW];   // cols 0..127 self, 128..255 neigh

    const int tid  = threadIdx.x;
    const int wi   = tid >> 5;
    const int lane = tid & 31;
    const int mt   = blockIdx.x;            // 0..1249
    const int ebase = mt * 512;

    eb[tid]       = make_int2(col[ebase + tid],       __float_as_int(ew[ebase + tid]));
    eb[tid + 256] = make_int2(col[ebase + 256 + tid], __float_as_int(ew[ebase + 256 + tid]));
    __syncthreads();

    // phase 1: warp wi handles local nodes wi*2, wi*2+1
    #pragma unroll
    for (int s = 0; s < 2; s++) {
        const int ln   = wi * 2 + s;
        const int node = mt * 16 + ln;

        float4 sv = *reinterpret_cast<const float4*>(
            x + (size_t)node * D_IN + lane * 4);
        *reinterpret_cast<float4*>(&rows[ln][lane * 4]) = sv;

        u64 acc0 = 0ull, acc1 = 0ull;
        float deg = 0.f;
        #pragma unroll 8
        for (int e = 0; e < DEG; e++) {
            const int2 cw = eb[ln * DEG + e];
            const float w = __int_as_float(cw.y);
            deg += w;
            ulonglong2 v = *reinterpret_cast<const ulonglong2*>(
                x + (size_t)cw.x * D_IN + lane * 4);
            const u64 wd = dup2(w);
            fma2(acc0, wd, v.x);
            fma2(acc1, wd, v.y);
        }
        if (deg == 0.f) deg = 1.f;
        const u64 iv = dup2(1.f / deg);
        acc0 = mul2(acc0, iv);
        acc1 = mul2(acc1, iv);
        float f0, f1, f2, f3;
        unpack2(f0, f1, acc0);
        unpack2(f2, f3, acc1);
        *reinterpret_cast<float4*>(&rows[ln][D_IN + lane * 4]) =
            make_float4(f0, f1, f2, f3);
    }
    __syncthreads();

    // phase 2: emit fragment-major Ah/Al; warp wi -> ktiles wi and wi+8
    const int r   = lane >> 2;
    const int kc0 = (lane & 3) * 2;
    #pragma unroll
    for (int it = 0; it < 2; it++) {
        const int kt = wi + it * 8;
        const float* rp0 = &rows[r][kt * 16 + kc0];
        const float* rp1 = &rows[r + 8][kt * 16 + kc0];
        float2 v00 = *reinterpret_cast<const float2*>(rp0);      // (r,  c0..c0+1)
        float2 v10 = *reinterpret_cast<const float2*>(rp1);      // (r+8,c0..c0+1)
        float2 v01 = *reinterpret_cast<const float2*>(rp0 + 8);  // (r,  c0+8..9)
        float2 v11 = *reinterpret_cast<const float2*>(rp1 + 8);  // (r+8,c0+8..9)

        __nv_bfloat16 h[8], l[8];
        split_bf(v00.x, h[0], l[0]); split_bf(v00.y, h[1], l[1]);
        split_bf(v10.x, h[2], l[2]); split_bf(v10.y, h[3], l[3]);
        split_bf(v01.x, h[4], l[4]); split_bf(v01.y, h[5], l[5]);
        split_bf(v11.x, h[6], l[6]); split_bf(v11.y, h[7], l[7]);

        const size_t o = (size_t)(mt * 16 + kt) * 32 + lane;
        reinterpret_cast<uint4*>(g_Ah)[o] =
            make_uint4(pkbf(h[0],h[1]), pkbf(h[2],h[3]), pkbf(h[4],h[5]), pkbf(h[6],h[7]));
        reinterpret_cast<uint4*>(g_Al)[o] =
            make_uint4(pkbf(l[0],l[1]), pkbf(l[2],l[3]), pkbf(l[4],l[5]), pkbf(l[6],l[7]));
    }
}

// ------------- Kernel 2: W -> fragment-major B images ------------------------
__global__ __launch_bounds__(256)
void wconv_kernel(const float* __restrict__ Wl, const float* __restrict__ Wr)
{
    const int gid = blockIdx.x * 256 + threadIdx.x;   // 32768 = 128 kpairs x 256 n
    const int kp  = gid >> 8;            // 0..127
    const int n   = gid & 255;
    const int ke  = kp * 2;              // even k

    const float v0 = (ke < D_IN) ? Wl[(size_t)ke * D_OUT + n]
                                 : Wr[(size_t)(ke - D_IN) * D_OUT + n];
    const float v1 = (ke + 1 < D_IN) ? Wl[(size_t)(ke + 1) * D_OUT + n]
                                     : Wr[(size_t)(ke + 1 - D_IN) * D_OUT + n];
    __nv_bfloat16 h0, h1, l0, l1;
    split_bf(v0, h0, l0);
    split_bf(v1, h1, l1);

    const int K    = ke >> 4;
    const int kc   = ke & 15;
    const int G    = n >> 6;
    const int t    = (n >> 3) & 7;
    const int p    = t >> 1;
    const int tsel = t & 1;
    const int fl   = ((n & 7) << 2) | ((kc & 7) >> 1);
    const int comp = (tsel << 1) | (kc >> 3);
    const size_t o = ((size_t)((K * 16 + G * 4 + p) * 32 + fl) << 2) | comp;

    reinterpret_cast<uint32_t*>(g_Bh)[o] = pkbf(h0, h1);
    reinterpret_cast<uint32_t*>(g_Bl)[o] = pkbf(l0, l1);
}

// ------------- Kernel 3: bf16-split mma.sync GEMM ---------------------------
__device__ __forceinline__ void mma_bf16(float* c, const uint4& a,
                                         uint32_t b0, uint32_t b1)
{
    asm volatile(
        "mma.sync.aligned.m16n8k16.row.col.f32.bf16.bf16.f32 "
        "{%0,%1,%2,%3}, {%4,%5,%6,%7}, {%8,%9}, {%0,%1,%2,%3};"
        : "+f"(c[0]), "+f"(c[1]), "+f"(c[2]), "+f"(c[3])
        : "r"(a.x), "r"(a.y), "r"(a.z), "r"(a.w), "r"(b0), "r"(b1));
}

#define MMA3(C, AH, AL, BH0, BH1, BL0, BL1) \
    do { mma_bf16(C, AH, BH0, BH1); mma_bf16(C, AH, BL0, BL1); \
         mma_bf16(C, AL, BH0, BH1); } while (0)

__global__ __launch_bounds__(256)
void mma_gemm_kernel(const float* __restrict__ bias, float* __restrict__ out)
{
    const int tid  = threadIdx.x;
    const int lane = tid & 31;
    const int wid  = tid >> 5;
    const int mw   = wid >> 1;
    const int nw   = wid & 1;
    const int mtile = blockIdx.x * 4 + mw;
    if (mtile >= MTILES) return;                   // no smem / syncs in kernel
    const int G = blockIdx.y * 2 + nw;             // 0..3 (n64 group)

    const uint4* pAh = reinterpret_cast<const uint4*>(g_Ah)
                       + (size_t)mtile * 16 * 32 + lane;
    const uint4* pAl = reinterpret_cast<const uint4*>(g_Al)
                       + (size_t)mtile * 16 * 32 + lane;
    const uint4* pBh = reinterpret_cast<const uint4*>(g_Bh);
    const uint4* pBl = reinterpret_cast<const uint4*>(g_Bl);

    float acc[8][4];
    #pragma unroll
    for (int t = 0; t < 8; t++)
        #pragma unroll
        for (int i = 0; i < 4; i++) acc[t][i] = 0.f;

    #pragma unroll 4
    for (int kt = 0; kt < 16; kt++) {
        const uint4 ah = pAh[kt * 32];
        const uint4 al = pAl[kt * 32];
        const int bb = (kt * 16 + G * 4) * 32 + lane;
        const uint4 bh0 = pBh[bb], bh1 = pBh[bb + 32],
                    bh2 = pBh[bb + 64], bh3 = pBh[bb + 96];
        const uint4 bl0 = pBl[bb], bl1 = pBl[bb + 32],
                    bl2 = pBl[bb + 64], bl3 = pBl[bb + 96];

        MMA3(acc[0], ah, al, bh0.x, bh0.y, bl0.x, bl0.y);
        MMA3(acc[1], ah, al, bh0.z, bh0.w, bl0.z, bl0.w);
        MMA3(acc[2], ah, al, bh1.x, bh1.y, bl1.x, bl1.y);
        MMA3(acc[3], ah, al, bh1.z, bh1.w, bl1.z, bl1.w);
        MMA3(acc[4], ah, al, bh2.x, bh2.y, bl2.x, bl2.y);
        MMA3(acc[5], ah, al, bh2.z, bh2.w, bl2.z, bl2.w);
        MMA3(acc[6], ah, al, bh3.x, bh3.y, bl3.x, bl3.y);
        MMA3(acc[7], ah, al, bh3.z, bh3.w, bl3.z, bl3.w);
    }

    // epilogue: C frag (m16n8): c0,c1 -> row=lane>>2, cols +0,+1; c2,c3 -> row+8
    const int row0 = mtile * 16 + (lane >> 2);
    const int cb   = G * 64 + (lane & 3) * 2;
    #pragma unroll
    for (int t = 0; t < 8; t++) {
        const int cc = cb + t * 8;
        const float2 bia = *reinterpret_cast<const float2*>(bias + cc);
        float2 o0, o1;
        o0.x = acc[t][0] + bia.x;  o0.y = acc[t][1] + bia.y;
        o1.x = acc[t][2] + bia.x;  o1.y = acc[t][3] + bia.y;
        *reinterpret_cast<float2*>(out + (size_t)row0 * D_OUT + cc)       = o0;
        *reinterpret_cast<float2*>(out + (size_t)(row0 + 8) * D_OUT + cc) = o1;
    }
}

extern "C" void kernel_launch(void* const* d_in, const int* in_sizes, int n_in,
                              void* d_out, int out_size)
{
    const float* x  = (const float*)d_in[0];
    const int*   ei = (const int*)  d_in[1];   // [2, E]
    const float* ew = (const float*)d_in[2];
    const float* Wl = (const float*)d_in[3];
    const float* bl = (const float*)d_in[4];
    const float* Wr = (const float*)d_in[5];
    float*       out = (float*)d_out;

    const int* col = ei + E_EDGES;             // second row of edge_index

    gather_kernel<<<MTILES, 256>>>(x, col, ew);
    wconv_kernel<<<128, 256>>>(Wl, Wr);

    dim3 g((MTILES + 3) / 4, 2);               // (313, 2)
    mma_gemm_kernel<<<g, 256>>>(bl, out);
}

// round 9
// speedup vs baseline: 4.1436x; 1.4383x over previous
#include <cuda_runtime.h>
#include <cuda_fp16.h>
#include <cstdint>
#include <cstddef>

#define N_NODES 20000
#define DEG     32
#define D_IN    128
#define D_OUT   256
#define E_EDGES (N_NODES * DEG)
#define MTILES  1250             // 20000 / 16 exactly

// A image in mma.sync fragment-major layout (fp16):
//   uint4 index = (mtile*16 + ktile)*32 + lane ; holds {a0,a1,a2,a3}
__device__ __half g_A[(size_t)N_NODES * D_OUT];
// B image (256x256) fragment-major (fp16):
//   uint4 index = (ktile*16 + G*4 + p)*32 + lane ; comps = {t(2p).b0,t(2p).b1,t(2p+1).b0,t(2p+1).b1}
__device__ __half g_B[D_OUT * D_OUT];

typedef unsigned long long u64;

__device__ __forceinline__ u64 dup2(float a) {
    u64 r; asm("mov.b64 %0, {%1, %1};" : "=l"(r) : "f"(a)); return r;
}
__device__ __forceinline__ void fma2(u64& d, u64 a, u64 b) {
    asm("fma.rn.f32x2 %0, %1, %2, %0;" : "+l"(d) : "l"(a), "l"(b));
}
__device__ __forceinline__ u64 mul2(u64 a, u64 b) {
    u64 r; asm("mul.rn.f32x2 %0, %1, %2;" : "=l"(r) : "l"(a), "l"(b)); return r;
}
__device__ __forceinline__ void unpack2(float& lo, float& hi, u64 v) {
    asm("mov.b64 {%0, %1}, %2;" : "=f"(lo), "=f"(hi) : "l"(v));
}
__device__ __forceinline__ uint32_t pkhf(float a, float b) {
    __half2 h = __floats2half2_rn(a, b);
    return *reinterpret_cast<uint32_t*>(&h);
}

// ------------- Kernel 1: gather + frag-layout fp16 A image ------------------
#define SROW 260   // padded row stride (floats)

__global__ __launch_bounds__(256)
void gather_kernel(const float* __restrict__ x,
                   const int*   __restrict__ col,
                   const float* __restrict__ ew)
{
    __shared__ int2  eb[512];
    __shared__ float rows[16][SROW];   // cols 0..127 self, 128..255 neigh

    const int tid  = threadIdx.x;
    const int wi   = tid >> 5;
    const int lane = tid & 31;
    const int mt   = blockIdx.x;            // 0..1249
    const int ebase = mt * 512;

    eb[tid]       = make_int2(col[ebase + tid],       __float_as_int(ew[ebase + tid]));
    eb[tid + 256] = make_int2(col[ebase + 256 + tid], __float_as_int(ew[ebase + 256 + tid]));
    __syncthreads();

    // phase 1: warp wi handles local nodes ln0 = wi*2, ln1 = wi*2+1, interleaved
    const int ln0 = wi * 2, ln1 = ln0 + 1;
    {
        float4 s0 = *reinterpret_cast<const float4*>(
            x + (size_t)(mt * 16 + ln0) * D_IN + lane * 4);
        float4 s1 = *reinterpret_cast<const float4*>(
            x + (size_t)(mt * 16 + ln1) * D_IN + lane * 4);
        *reinterpret_cast<float4*>(&rows[ln0][lane * 4]) = s0;
        *reinterpret_cast<float4*>(&rows[ln1][lane * 4]) = s1;
    }
    {
        u64 a00 = 0ull, a01 = 0ull, a10 = 0ull, a11 = 0ull;
        float d0 = 0.f, d1 = 0.f;
        #pragma unroll 4
        for (int e = 0; e < DEG; e++) {
            const int2 c0 = eb[ln0 * DEG + e];
            const int2 c1 = eb[ln1 * DEG + e];
            const float w0 = __int_as_float(c0.y);
            const float w1 = __int_as_float(c1.y);
            d0 += w0; d1 += w1;
            ulonglong2 v0 = *reinterpret_cast<const ulonglong2*>(
                x + (size_t)c0.x * D_IN + lane * 4);
            ulonglong2 v1 = *reinterpret_cast<const ulonglong2*>(
                x + (size_t)c1.x * D_IN + lane * 4);
            const u64 wd0 = dup2(w0), wd1 = dup2(w1);
            fma2(a00, wd0, v0.x); fma2(a01, wd0, v0.y);
            fma2(a10, wd1, v1.x); fma2(a11, wd1, v1.y);
        }
        if (d0 == 0.f) d0 = 1.f;
        if (d1 == 0.f) d1 = 1.f;
        const u64 i0 = dup2(1.f / d0), i1 = dup2(1.f / d1);
        a00 = mul2(a00, i0); a01 = mul2(a01, i0);
        a10 = mul2(a10, i1); a11 = mul2(a11, i1);
        float f0, f1, f2, f3;
        unpack2(f0, f1, a00); unpack2(f2, f3, a01);
        *reinterpret_cast<float4*>(&rows[ln0][D_IN + lane * 4]) =
            make_float4(f0, f1, f2, f3);
        unpack2(f0, f1, a10); unpack2(f2, f3, a11);
        *reinterpret_cast<float4*>(&rows[ln1][D_IN + lane * 4]) =
            make_float4(f0, f1, f2, f3);
    }
    __syncthreads();

    // phase 2: emit fragment-major fp16 A; warp wi -> ktiles wi and wi+8
    const int r   = lane >> 2;
    const int kc0 = (lane & 3) * 2;
    #pragma unroll
    for (int it = 0; it < 2; it++) {
        const int kt = wi + it * 8;
        const float* rp0 = &rows[r][kt * 16 + kc0];
        const float* rp1 = &rows[r + 8][kt * 16 + kc0];
        float2 v00 = *reinterpret_cast<const float2*>(rp0);      // (r,  c0..c0+1) -> a0
        float2 v10 = *reinterpret_cast<const float2*>(rp1);      // (r+8,c0..c0+1) -> a1
        float2 v01 = *reinterpret_cast<const float2*>(rp0 + 8);  // (r,  c0+8..9)  -> a2
        float2 v11 = *reinterpret_cast<const float2*>(rp1 + 8);  // (r+8,c0+8..9)  -> a3

        const size_t o = (size_t)(mt * 16 + kt) * 32 + lane;
        reinterpret_cast<uint4*>(g_A)[o] =
            make_uint4(pkhf(v00.x, v00.y), pkhf(v10.x, v10.y),
                       pkhf(v01.x, v01.y), pkhf(v11.x, v11.y));
    }
}

// ------------- Kernel 2: W -> fragment-major fp16 B image --------------------
__global__ __launch_bounds__(256)
void wconv_kernel(const float* __restrict__ Wl, const float* __restrict__ Wr)
{
    const int gid = blockIdx.x * 256 + threadIdx.x;   // 32768 = 128 kpairs x 256 n
    const int kp  = gid >> 8;            // 0..127
    const int n   = gid & 255;
    const int ke  = kp * 2;              // even k

    const float v0 = (ke < D_IN) ? Wl[(size_t)ke * D_OUT + n]
                                 : Wr[(size_t)(ke - D_IN) * D_OUT + n];
    const float v1 = (ke + 1 < D_IN) ? Wl[(size_t)(ke + 1) * D_OUT + n]
                                     : Wr[(size_t)(ke + 1 - D_IN) * D_OUT + n];

    const int K    = ke >> 4;
    const int kc   = ke & 15;
    const int G    = n >> 6;
    const int t    = (n >> 3) & 7;
    const int p    = t >> 1;
    const int tsel = t & 1;
    const int fl   = ((n & 7) << 2) | ((kc & 7) >> 1);
    const int comp = (tsel << 1) | (kc >> 3);
    const size_t o = ((size_t)((K * 16 + G * 4 + p) * 32 + fl) << 2) | comp;

    reinterpret_cast<uint32_t*>(g_B)[o] = pkhf(v0, v1);
}

// ------------- Kernel 3: pure fp16 mma.sync GEMM ----------------------------
__device__ __forceinline__ void mma_f16(float* c, const uint4& a,
                                        uint32_t b0, uint32_t b1)
{
    asm volatile(
        "mma.sync.aligned.m16n8k16.row.col.f32.f16.f16.f32 "
        "{%0,%1,%2,%3}, {%4,%5,%6,%7}, {%8,%9}, {%0,%1,%2,%3};"
        : "+f"(c[0]), "+f"(c[1]), "+f"(c[2]), "+f"(c[3])
        : "r"(a.x), "r"(a.y), "r"(a.z), "r"(a.w), "r"(b0), "r"(b1));
}

__global__ __launch_bounds__(256)
void mma_gemm_kernel(const float* __restrict__ bias, float* __restrict__ out)
{
    const int tid  = threadIdx.x;
    const int lane = tid & 31;
    const int wid  = tid >> 5;
    const int mw   = wid >> 1;
    const int nw   = wid & 1;
    const int mtile = blockIdx.x * 4 + mw;
    if (mtile >= MTILES) return;                   // no smem / syncs in kernel
    const int G = blockIdx.y * 2 + nw;             // 0..3 (n64 group)

    const uint4* pA = reinterpret_cast<const uint4*>(g_A)
                      + (size_t)mtile * 16 * 32 + lane;
    const uint4* pB = reinterpret_cast<const uint4*>(g_B);

    float acc[8][4];
    #pragma unroll
    for (int t = 0; t < 8; t++)
        #pragma unroll
        for (int i = 0; i < 4; i++) acc[t][i] = 0.f;

    #pragma unroll 4
    for (int kt = 0; kt < 16; kt++) {
        const uint4 a = pA[kt * 32];
        const int bb = (kt * 16 + G * 4) * 32 + lane;
        const uint4 b0 = pB[bb],      b1 = pB[bb + 32],
                    b2 = pB[bb + 64], b3 = pB[bb + 96];

        mma_f16(acc[0], a, b0.x, b0.y);
        mma_f16(acc[1], a, b0.z, b0.w);
        mma_f16(acc[2], a, b1.x, b1.y);
        mma_f16(acc[3], a, b1.z, b1.w);
        mma_f16(acc[4], a, b2.x, b2.y);
        mma_f16(acc[5], a, b2.z, b2.w);
        mma_f16(acc[6], a, b3.x, b3.y);
        mma_f16(acc[7], a, b3.z, b3.w);
    }

    // epilogue: C frag (m16n8): c0,c1 -> row=lane>>2, cols +0,+1; c2,c3 -> row+8
    const int row0 = mtile * 16 + (lane >> 2);
    const int cb   = G * 64 + (lane & 3) * 2;
    #pragma unroll
    for (int t = 0; t < 8; t++) {
        const int cc = cb + t * 8;
        const float2 bia = *reinterpret_cast<const float2*>(bias + cc);
        float2 o0, o1;
        o0.x = acc[t][0] + bia.x;  o0.y = acc[t][1] + bia.y;
        o1.x = acc[t][2] + bia.x;  o1.y = acc[t][3] + bia.y;
        *reinterpret_cast<float2*>(out + (size_t)row0 * D_OUT + cc)       = o0;
        *reinterpret_cast<float2*>(out + (size_t)(row0 + 8) * D_OUT + cc) = o1;
    }
}

extern "C" void kernel_launch(void* const* d_in, const int* in_sizes, int n_in,
                              void* d_out, int out_size)
{
    const float* x  = (const float*)d_in[0];
    const int*   ei = (const int*)  d_in[1];   // [2, E]
    const float* ew = (const float*)d_in[2];
    const float* Wl = (const float*)d_in[3];
    const float* bl = (const float*)d_in[4];
    const float* Wr = (const float*)d_in[5];
    float*       out = (float*)d_out;

    const int* col = ei + E_EDGES;             // second row of edge_index

    gather_kernel<<<MTILES, 256>>>(x, col, ew);
    wconv_kernel<<<128, 256>>>(Wl, Wr);

    dim3 g((MTILES + 3) / 4, 2);               // (313, 2)
    mma_gemm_kernel<<<g, 256>>>(bl, out);
}